// round 6
// baseline (speedup 1.0000x reference)
#include <cuda_runtime.h>
#include <cstdint>

#define BB 64
#define NN 1024

// Output layout (flattened reference tuple, all float32):
#define OFF_DONE 0
#define OFF_NM   1
#define OFF_ADJ  (1 + BB*NN)
#define OFF_FA   (OFF_ADJ + (size_t)BB*NN*NN)
#define OFF_PT   (OFF_FA + BB)
#define OFF_STEP (OFF_PT + BB)

__device__ float g_fp[BB * NN];     // fpresent[b, i]
__device__ float g_dlast[NN];       // dist[:, N-1] contiguous
__device__ float g_nmlast[BB];      // new_mask[b, N-1] (for `done` reduction)

__global__ void k_prep(const float* __restrict__ inputs,
                       const float* __restrict__ dist,
                       const float* __restrict__ mask,
                       const float* __restrict__ ptime,
                       const int*   __restrict__ pres,
                       const int*   __restrict__ fut,
                       float* out)
{
    int b = blockIdx.x;
    int j = threadIdx.x;

    int   pa = pres[b];
    float pt = ptime[b];

    float4 in4 = *reinterpret_cast<const float4*>(inputs + ((size_t)(b * NN + j)) * 4);
    float op = in4.x, cl = in4.y, dur = in4.z;
    float T0 = inputs[3];

    float dlast  = dist[(size_t)j * NN + (NN - 1)];
    float arrive = dist[(size_t)pa * NN + j] + pt;
    float wait   = fmaxf(0.0f, op - arrive);
    float t      = arrive + wait;

    bool c1 = t <= cl;
    bool c2 = ((t + dur) + dlast) <= T0;

    float m = mask[b * NN + j];
    if (j == pa) m = 0.0f;
    float nm = (c1 && c2) ? m : 0.0f;

    float fpres = t + dur;

    out[OFF_NM + b * NN + j] = nm;
    g_fp[b * NN + j] = fpres;
    if (b == 0) g_dlast[j] = dlast;
    if (j == NN - 1) g_nmlast[b] = nm;

    int fb = fut[b];
    if (j == fb) out[OFF_PT + b] = fpres;
    if (j == 0) {
        out[OFF_FA + b]   = (float)fb;
        out[OFF_STEP + b] = 1.0f;
    }
}

// adj kernel — fully coalesced (j = tid + 256q), no smem, EXPLICIT load
// batching: per (batch, q-slice) all RR dist loads are issued back-to-back
// (structural MLP=RR) before any compute/store. 3 blocks/SM via
// launch_bounds(256,3) -> <=85 regs, no spills at ~55 live regs.
#define BT 4
#define RR 16

__global__ __launch_bounds__(256, 3) void k_adj(const float* __restrict__ inputs,
                                                const float* __restrict__ dist,
                                                float* out)
{
    const int ITILES = NN / RR;                 // 64
    int itile = blockIdx.x & (ITILES - 1);
    int b0    = (blockIdx.x / ITILES) * BT;
    int i0    = itile * RR;
    int tid   = threadIdx.x;

    if (blockIdx.x == 0 && tid == 0) {
        float any = 0.0f;
#pragma unroll
        for (int b = 0; b < BB; b++) any = fmaxf(any, g_nmlast[b]);
        out[OFF_DONE] = (any > 0.0f) ? 0.0f : 1.0f;
    }

    float dl[4];
#pragma unroll
    for (int q = 0; q < 4; q++) dl[q] = g_dlast[tid + 256 * q];

    const float* nm_base = out + OFF_NM;

    for (int bb = 0; bb < BT; bb++) {
        int b = b0 + bb;

        // Uniform per-row fpresent values for this batch's i-tile.
        float fp[RR];
#pragma unroll
        for (int r = 0; r < RR; r++) fp[r] = g_fp[b * NN + i0 + r];

        float Tb = inputs[((size_t)b * NN) * 4 + 3];

#pragma unroll
        for (int q = 0; q < 4; q++) {
            int j = tid + 256 * q;

            float4 in4 = *reinterpret_cast<const float4*>(
                inputs + ((size_t)(b * NN + j)) * 4);
            float op = in4.x, cl = in4.y, du = in4.z;
            float nm = nm_base[b * NN + j];

            // Front-batched dist loads: RR independent coalesced LDGs.
            float d[RR];
#pragma unroll
            for (int r = 0; r < RR; r++)
                d[r] = __ldg(dist + (size_t)(i0 + r) * NN + j);

#pragma unroll
            for (int r = 0; r < RR; r++) {
                int i = i0 + r;
                float arr2 = d[r] + fp[r];
                float w    = fmaxf(0.0f, op - arr2);
                float s    = arr2 + w;
                bool a1 = s <= cl;
                bool a2 = ((s + du) + dl[q]) <= Tb;
                float v = (a1 && a2) ? nm : 0.0f;
                if (j == i) v = 1.0f;
                out[OFF_ADJ + ((size_t)(b * NN + i)) * NN + j] = v;
            }
        }
    }
}

extern "C" void kernel_launch(void* const* d_in, const int* in_sizes, int n_in,
                              void* d_out, int out_size)
{
    const float* inputs = (const float*)d_in[0];   // (B, N, 4) f32
    const float* dist   = (const float*)d_in[1];   // (N, N)   f32
    const float* mask   = (const float*)d_in[2];   // (B, N)   f32
    const float* ptime  = (const float*)d_in[3];   // (B, 1)   f32
    const int*   pres   = (const int*)d_in[4];     // (B,)     i32
    const int*   fut    = (const int*)d_in[5];     // (B,)     i32
    float* out = (float*)d_out;

    k_prep<<<BB, NN>>>(inputs, dist, mask, ptime, pres, fut, out);
    k_adj<<<(NN / RR) * (BB / BT), 256>>>(inputs, dist, out);
}

// round 7
// speedup vs baseline: 1.5515x; 1.5515x over previous
#include <cuda_runtime.h>
#include <cstdint>

#define BB 64
#define NN 1024

// Output layout (flattened reference tuple, all float32):
#define OFF_DONE 0
#define OFF_NM   1
#define OFF_ADJ  (1 + BB*NN)
#define OFF_FA   (OFF_ADJ + (size_t)BB*NN*NN)
#define OFF_PT   (OFF_FA + BB)
#define OFF_STEP (OFF_PT + BB)

__device__ float g_fp[BB * NN];     // fpresent[b, i]
__device__ float g_dlast[NN];       // dist[:, N-1] contiguous
__device__ float g_nmlast[BB];      // new_mask[b, N-1] (for `done` reduction)

__global__ void k_prep(const float* __restrict__ inputs,
                       const float* __restrict__ dist,
                       const float* __restrict__ mask,
                       const float* __restrict__ ptime,
                       const int*   __restrict__ pres,
                       const int*   __restrict__ fut,
                       float* out)
{
    int b = blockIdx.x;
    int j = threadIdx.x;

    int   pa = pres[b];
    float pt = ptime[b];

    float4 in4 = *reinterpret_cast<const float4*>(inputs + ((size_t)(b * NN + j)) * 4);
    float op = in4.x, cl = in4.y, dur = in4.z;
    float T0 = inputs[3];

    float dlast  = dist[(size_t)j * NN + (NN - 1)];
    float arrive = dist[(size_t)pa * NN + j] + pt;
    float wait   = fmaxf(0.0f, op - arrive);
    float t      = arrive + wait;

    bool c1 = t <= cl;
    bool c2 = ((t + dur) + dlast) <= T0;

    float m = mask[b * NN + j];
    if (j == pa) m = 0.0f;
    float nm = (c1 && c2) ? m : 0.0f;

    float fpres = t + dur;

    out[OFF_NM + b * NN + j] = nm;
    g_fp[b * NN + j] = fpres;
    if (b == 0) g_dlast[j] = dlast;
    if (j == NN - 1) g_nmlast[b] = nm;

    int fb = fut[b];
    if (j == fb) out[OFF_PT + b] = fpres;
    if (j == 0) {
        out[OFF_FA + b]   = (float)fb;
        out[OFF_STEP + b] = 1.0f;
    }
}

// adj kernel — aligned-vector everything, no smem, no shuffle.
// adj base index ≡ 1 (mod 4), so the float4 at j = 4l+3 is 16B-aligned
// (same for new_mask). dist d[4l+3..4l+6] is assembled from TWO aligned
// float4 loads (j=4l, j=4l+4); the overlap is an L1 hit.
// Warp w owns j-window [128w, 128w+128): lanes 0..30 vector-handle
// j = 128w+3 .. 128w+126; the leftovers {128w+0,1,2,127} over all 8 warps
// (32 scalars per row) are gathered by ONE rotating warp, one lane each.
#define BT 4
#define RR 16

__global__ __launch_bounds__(256) void k_adj(const float* __restrict__ inputs,
                                             const float* __restrict__ dist,
                                             float* out)
{
    const int ITILES = NN / RR;                 // 64
    int itile = blockIdx.x & (ITILES - 1);
    int b0    = (blockIdx.x / ITILES) * BT;
    int i0    = itile * RR;
    int tid   = threadIdx.x;
    int warp  = tid >> 5;
    int lane  = tid & 31;
    int jw    = warp << 7;                      // 128 * warp

    if (blockIdx.x == 0 && tid == 0) {
        float any = 0.0f;
#pragma unroll
        for (int b = 0; b < BB; b++) any = fmaxf(any, g_nmlast[b]);
        out[OFF_DONE] = (any > 0.0f) ? 0.0f : 1.0f;
    }

    int  ls   = (lane < 31) ? lane : 30;        // lane 31 mirrors lane 30
    bool act  = (lane < 31);
    int  jb   = jw + 4 * ls + 3;                // 4 output elements jb..jb+3
    int  j2a  = jw + 4 * ls;                    // aligned dist load #1
    int  j2b  = j2a + 4;                        // aligned dist load #2 (<=jw+124)

    // leftover j handled by this lane when its warp is on duty
    int kw = lane >> 2, ke = lane & 3;
    int jL = (kw << 7) + ((ke == 3) ? 127 : ke);

    float dl[4];
#pragma unroll
    for (int e = 0; e < 4; e++) dl[e] = g_dlast[jb + e];
    float dlL = g_dlast[jL];

    const float* nm_base = out + OFF_NM;

    for (int bb = 0; bb < BT; bb++) {
        int b = b0 + bb;

        // fpresent for this i-tile (uniform across lanes), vector loads
        float fp_[RR];
        {
            const float4* fpp = reinterpret_cast<const float4*>(g_fp + b * NN + i0);
#pragma unroll
            for (int t = 0; t < RR / 4; t++) {
                float4 f = fpp[t];
                fp_[4*t+0] = f.x; fp_[4*t+1] = f.y;
                fp_[4*t+2] = f.z; fp_[4*t+3] = f.w;
            }
        }

        float Tb = inputs[((size_t)b * NN) * 4 + 3];

        float op[4], cl[4], du[4];
#pragma unroll
        for (int e = 0; e < 4; e++) {
            float4 i4 = *reinterpret_cast<const float4*>(
                inputs + ((size_t)(b * NN + jb + e)) * 4);
            op[e] = i4.x; cl[e] = i4.y; du[e] = i4.z;
        }
        float4 nm4 = *reinterpret_cast<const float4*>(nm_base + b * NN + jb);
        float nm[4] = {nm4.x, nm4.y, nm4.z, nm4.w};

        // leftover-slot inputs
        float4 iL = *reinterpret_cast<const float4*>(
            inputs + ((size_t)(b * NN + jL)) * 4);
        float nmL = nm_base[b * NN + jL];

#pragma unroll
        for (int r = 0; r < RR; r++) {
            int   i   = i0 + r;
            float fpr = fp_[r];
            const float* drow = dist + (size_t)i * NN;
            float* orow = out + OFF_ADJ + ((size_t)(b * NN + i)) * NN;

            float4 da = *reinterpret_cast<const float4*>(drow + j2a);
            float4 db = *reinterpret_cast<const float4*>(drow + j2b);
            float d[4] = {da.w, db.x, db.y, db.z};   // dist[i][jb..jb+3]

            float v[4];
#pragma unroll
            for (int e = 0; e < 4; e++) {
                float arr2 = d[e] + fpr;
                float w    = fmaxf(0.0f, op[e] - arr2);
                float s    = arr2 + w;
                bool a1 = s <= cl[e];
                bool a2 = ((s + du[e]) + dl[e]) <= Tb;
                float x = (a1 && a2) ? nm[e] : 0.0f;
                if (jb + e == i) x = 1.0f;
                v[e] = x;
            }
            if (act)
                *reinterpret_cast<float4*>(orow + jb) =
                    make_float4(v[0], v[1], v[2], v[3]);

            if (warp == (r & 7)) {                   // rotating leftover duty
                float arr2 = __ldg(drow + jL) + fpr;
                float w    = fmaxf(0.0f, iL.x - arr2);
                float s    = arr2 + w;
                bool a1 = s <= iL.y;
                bool a2 = ((s + iL.z) + dlL) <= Tb;
                float x = (a1 && a2) ? nmL : 0.0f;
                if (jL == i) x = 1.0f;
                orow[jL] = x;
            }
        }
    }
}

extern "C" void kernel_launch(void* const* d_in, const int* in_sizes, int n_in,
                              void* d_out, int out_size)
{
    const float* inputs = (const float*)d_in[0];   // (B, N, 4) f32
    const float* dist   = (const float*)d_in[1];   // (N, N)   f32
    const float* mask   = (const float*)d_in[2];   // (B, N)   f32
    const float* ptime  = (const float*)d_in[3];   // (B, 1)   f32
    const int*   pres   = (const int*)d_in[4];     // (B,)     i32
    const int*   fut    = (const int*)d_in[5];     // (B,)     i32
    float* out = (float*)d_out;

    k_prep<<<BB, NN>>>(inputs, dist, mask, ptime, pres, fut, out);
    k_adj<<<(NN / RR) * (BB / BT), 256>>>(inputs, dist, out);
}